// round 2
// baseline (speedup 1.0000x reference)
#include <cuda_runtime.h>

#define KDIM 64
#define SDIM 512
#define TILE_I 64
#define TILE_S 128
#define PITCH 68          // floats per smem row: 272B (16B aligned)
#define NT 256
#define NTILES (SDIM / TILE_S)
#define MAXBLOCKS 2048

typedef unsigned long long ull;

__device__ float g_cbnorm[SDIM];
__device__ float g_partial[MAXBLOCKS];

__device__ __forceinline__ void ffma2(ull& d, ull a, ull b) {
    asm volatile("fma.rn.f32x2 %0, %1, %2, %0;" : "+l"(d) : "l"(a), "l"(b));
}
__device__ __forceinline__ void cp16(float* dst, const float* src) {
    unsigned d = (unsigned)__cvta_generic_to_shared(dst);
    asm volatile("cp.async.cg.shared.global [%0], [%1], 16;" :: "r"(d), "l"(src));
}
__device__ __forceinline__ void cp_commit() { asm volatile("cp.async.commit_group;"); }

// ---------------------------------------------------------------------------
// Prep: per-codeword squared norms
// ---------------------------------------------------------------------------
__global__ void vq_prep(const float* __restrict__ cb) {
    int s = blockIdx.x * blockDim.x + threadIdx.x;
    if (s < SDIM) {
        const float4* r = (const float4*)(cb + (long)s * KDIM);
        float acc = 0.f;
        #pragma unroll
        for (int q = 0; q < KDIM / 4; q++) {
            float4 v = r[q];
            acc = fmaf(v.x, v.x, acc);
            acc = fmaf(v.y, v.y, acc);
            acc = fmaf(v.z, v.z, acc);
            acc = fmaf(v.w, v.w, acc);
        }
        g_cbnorm[s] = acc;
    }
}

// ---------------------------------------------------------------------------
// Main: tiled fp32x2 GEMM + fused argmin (reference-rounding) + gather + loss
// CTA: 64 vectors x 512 codewords (4 s-tiles of 128, double buffered)
// Thread tile: 4 vectors x 8 codewords, f32x2 packed along K
// Score d = fl(fl(vn - 2*dot) + cn), argmin tie-break = lowest s (packed key)
// ---------------------------------------------------------------------------
__global__ void __launch_bounds__(NT, 2)
vq_main(const float* __restrict__ vecs, const float* __restrict__ cb,
        float* __restrict__ out, int N)
{
    extern __shared__ float sm[];
    float* vt   = sm;                                   // TILE_I * PITCH
    float* ct   = vt + TILE_I * PITCH;                  // 2 * TILE_S * PITCH
    ull*   kbuf = (ull*)(ct + 2 * TILE_S * PITCH);      // 64 * 17 (8B aligned: offset 87040B)
    float* sv   = (float*)(kbuf + 64 * 17);             // 64 per-vector ||v||^2
    int*   bidx = (int*)(sv + 64);                      // 64
    float* redsum = (float*)(bidx + 64);                // 64

    const int tid = threadIdx.x;
    const int tx = tid & 15;      // codeword direction (16 threads)
    const int ty = tid >> 4;      // vector direction   (16 threads)
    const long i0 = (long)blockIdx.x * TILE_I;

    // Prologue: async-load vector tile + first codebook tile (group 0)
    {
        const float* vsrc = vecs + i0 * KDIM;
        for (int n = tid; n < TILE_I * (KDIM / 4); n += NT) {
            int row = n >> 4, c4 = n & 15;
            cp16(vt + row * PITCH + c4 * 4, vsrc + row * KDIM + c4 * 4);
        }
        for (int n = tid; n < TILE_S * (KDIM / 4); n += NT) {
            int row = n >> 4, c4 = n & 15;
            cp16(ct + row * PITCH + c4 * 4, cb + row * KDIM + c4 * 4);
        }
        cp_commit();
    }

    // Per-vector squared norms directly from gmem (overlaps with cp.async).
    // Sequential fp32 FMA over k = 0..63.
    if (tid < TILE_I) {
        const float4* r = (const float4*)(vecs + (i0 + tid) * KDIM);
        float acc = 0.f;
        #pragma unroll
        for (int q = 0; q < KDIM / 4; q++) {
            float4 v = __ldg(r + q);
            acc = fmaf(v.x, v.x, acc);
            acc = fmaf(v.y, v.y, acc);
            acc = fmaf(v.z, v.z, acc);
            acc = fmaf(v.w, v.w, acc);
        }
        sv[tid] = acc;
    }

    ull bestkey = ~0ull;   // running (score|index) min for vector `tid` (tid<64)

    for (int t = 0; t < NTILES; ++t) {
        // Prefetch next codebook tile, then wait for current one
        if (t + 1 < NTILES) {
            const float* csrc = cb + (long)(t + 1) * TILE_S * KDIM;
            float* cdst = ct + ((t + 1) & 1) * TILE_S * PITCH;
            for (int n = tid; n < TILE_S * (KDIM / 4); n += NT) {
                int row = n >> 4, c4 = n & 15;
                cp16(cdst + row * PITCH + c4 * 4, csrc + row * KDIM + c4 * 4);
            }
            cp_commit();
            asm volatile("cp.async.wait_group 1;");
        } else {
            asm volatile("cp.async.wait_group 0;");
        }
        __syncthreads();   // also publishes sv[] on t==0

        const float* cbt  = ct + (t & 1) * TILE_S * PITCH;
        const float* vrow = vt + (ty * 4) * PITCH;
        const float* crow = cbt + tx * PITCH;

        ull acc[4][8];
        #pragma unroll
        for (int a = 0; a < 4; a++)
            #pragma unroll
            for (int b = 0; b < 8; b++) acc[a][b] = 0ull;

        #pragma unroll 4
        for (int kp = 0; kp < KDIM / 2; ++kp) {
            ull av[4], bv[8];
            #pragma unroll
            for (int ii = 0; ii < 4; ii++)
                av[ii] = *(const ull*)(vrow + ii * PITCH + kp * 2);
            #pragma unroll
            for (int jj = 0; jj < 8; jj++)
                bv[jj] = *(const ull*)(crow + jj * 16 * PITCH + kp * 2);
            #pragma unroll
            for (int ii = 0; ii < 4; ii++)
                #pragma unroll
                for (int jj = 0; jj < 8; jj++)
                    ffma2(acc[ii][jj], av[ii], bv[jj]);
        }

        // Per-thread min over its 8 codewords with reference rounding:
        //   d = fl( fl(vn - 2*dot) + cn ),  key = (bits(d)<<32) | s
        #pragma unroll
        for (int ii = 0; ii < 4; ii++) {
            float vn = sv[ty * 4 + ii];
            ull bk = ~0ull;
            #pragma unroll
            for (int jj = 0; jj < 8; jj++) {
                float lo = __uint_as_float((unsigned)(acc[ii][jj] & 0xffffffffull));
                float hi = __uint_as_float((unsigned)(acc[ii][jj] >> 32));
                float dot = lo + hi;
                int s = t * TILE_S + jj * 16 + tx;
                float t1 = __fmaf_rn(-2.0f, dot, vn);          // fl(vn - 2*dot)
                float d  = __fadd_rn(t1, __ldg((const float*)g_cbnorm + s));
                ull key = ((ull)__float_as_uint(d) << 32) | (unsigned)s;
                bk = min(bk, key);
            }
            kbuf[(ty * 4 + ii) * 17 + tx] = bk;
        }
        __syncthreads();
        // Cross-thread merge (one thread per vector keeps running best)
        if (tid < TILE_I) {
            #pragma unroll
            for (int x = 0; x < 16; x++)
                bestkey = min(bestkey, kbuf[tid * 17 + x]);
        }
        __syncthreads();
    }

    // Final epilogue: err, z, loss partial
    float* out_z = out + (long)N * KDIM;
    if (tid < TILE_I) {
        float d = __uint_as_float((unsigned)(bestkey >> 32));
        int   z = (int)(bestkey & 0xffffffffull);
        float err = fmaxf(d, 0.0f);
        out_z[i0 + tid] = (float)z;
        bidx[tid] = z;
        redsum[tid] = err;
    }
    __syncthreads();

    // Gather codewords: vecs_hat = codebook[z]
    for (int n = tid; n < TILE_I * KDIM; n += NT) {
        int row = n >> 6, col = n & 63;
        out[(i0 + row) * KDIM + col] = __ldg(&cb[(long)bidx[row] * KDIM + col]);
    }

    if (tid == 0) {
        float s = 0.f;
        #pragma unroll 8
        for (int x = 0; x < TILE_I; x++) s += redsum[x];
        g_partial[blockIdx.x] = s;
    }
}

// ---------------------------------------------------------------------------
// Final: deterministic reduction of per-CTA partials -> both loss scalars
// ---------------------------------------------------------------------------
__global__ void vq_final(float* __restrict__ out, int N, int nblocks) {
    __shared__ float smr[256];
    float s = 0.f;
    for (int i = threadIdx.x; i < nblocks; i += 256) s += g_partial[i];
    smr[threadIdx.x] = s;
    __syncthreads();
    if (threadIdx.x == 0) {
        double tot = 0.0;
        for (int i = 0; i < 256; i++) tot += (double)smr[i];
        float mean = (float)(tot / (double)N);
        long base = (long)N * KDIM + N;
        out[base]     = mean;   // l_commit
        out[base + 1] = mean;   // l_codebook (identical forward value)
    }
}

extern "C" void kernel_launch(void* const* d_in, const int* in_sizes, int n_in,
                              void* d_out, int out_size) {
    const float* vecs = (const float*)d_in[0];
    const float* cb   = (const float*)d_in[1];
    float* out = (float*)d_out;

    int N = in_sizes[0] / KDIM;          // 65536
    int nblocks = N / TILE_I;            // 1024

    size_t smem_bytes =
        (size_t)(TILE_I * PITCH + 2 * TILE_S * PITCH) * sizeof(float)
        + (size_t)(64 * 17) * sizeof(ull)
        + (size_t)64 * sizeof(float)     // sv
        + (size_t)64 * sizeof(int)       // bidx
        + (size_t)64 * sizeof(float);    // redsum

    cudaFuncSetAttribute(vq_main, cudaFuncAttributeMaxDynamicSharedMemorySize,
                         (int)smem_bytes);

    vq_prep<<<(SDIM + 255) / 256, 256>>>(cb);
    vq_main<<<nblocks, NT, smem_bytes>>>(vecs, cb, out, N);
    vq_final<<<1, 256>>>(out, N, nblocks);
}